// round 3
// baseline (speedup 1.0000x reference)
#include <cuda_runtime.h>

// Problem constants (fixed by the reference)
#define B_DIM 4096
#define E_DIM 1024
#define O_DIM 16
#define H_DIM 1024
#define KOH   (O_DIM * H_DIM)   // row stride of W[k, o, h] in floats

// GEMM tiling
#define TM 128
#define TN 128
#define BK 8
#define NTHREADS 256
#define MAX_TILES (B_DIM / TM + O_DIM)   // 32 + 16 = 48 (upper bound on sum ceil(c_o/TM))

// ---- device scratch (allocation-free: __device__ globals) ----
__device__ int   g_perm[B_DIM];
__device__ int   g_tile_op[MAX_TILES];
__device__ int   g_tile_start[MAX_TILES];
__device__ int   g_tile_rows[MAX_TILES];
__device__ int   g_num_tiles;
__device__ float g_h1[(size_t)B_DIM * H_DIM];   // 16 MB intermediate, permuted row order

// ============================================================================
// Setup: group examples by op. Builds perm[] (rows sorted by op) and row-tile
// descriptors so each 128-row GEMM tile belongs to exactly one op.
// ============================================================================
__global__ void setup_kernel(const int* __restrict__ op_idx)
{
    __shared__ int cnt[O_DIM];
    __shared__ int cur[O_DIM];
    const int tid = threadIdx.x;
    const int nt  = blockDim.x;

    if (tid < O_DIM) cnt[tid] = 0;
    __syncthreads();

    for (int b = tid; b < B_DIM; b += nt)
        atomicAdd(&cnt[op_idx[b]], 1);
    __syncthreads();

    if (tid == 0) {
        int acc = 0, ntile = 0;
        for (int o = 0; o < O_DIM; o++) {
            cur[o] = acc;
            const int c = cnt[o];
            for (int t = 0; t < c; t += TM) {
                g_tile_op[ntile]    = o;
                g_tile_start[ntile] = acc + t;
                g_tile_rows[ntile]  = (c - t < TM) ? (c - t) : TM;
                ntile++;
            }
            acc += c;
        }
        g_num_tiles = ntile;
    }
    __syncthreads();

    for (int b = tid; b < B_DIM; b += nt) {
        const int o = op_idx[b];
        const int p = atomicAdd(&cur[o], 1);
        g_perm[p] = b;
    }
}

// ============================================================================
// Grouped GEMM + bias + relu.
//   LAYER 1: A = x (rows gathered via perm), Out = g_h1 (permuted order)
//   LAYER 2: A = g_h1 (already permuted/contiguous), Out = out (scatter via perm)
// W layout: [K, O, N] with strides (O*N, N, 1); K = N = 1024 for both layers.
// ============================================================================
template <int LAYER>
__global__ __launch_bounds__(NTHREADS, 2)
void gemm_kernel(const float* __restrict__ A,
                 const float* __restrict__ W,
                 const float* __restrict__ bias,
                 float* __restrict__ Out)
{
    const int tile = blockIdx.x;
    if (tile >= g_num_tiles) return;

    const int op        = g_tile_op[tile];
    const int row_start = g_tile_start[tile];
    const int nrows     = g_tile_rows[tile];
    const int col_base  = blockIdx.y * TN;
    const int tid       = threadIdx.x;

    __shared__ float As[BK][TM];
    __shared__ float Bs[BK][TN];

    // A-tile load mapping: 128 rows x 8 k, one float4 per thread
    const int arow  = tid >> 1;          // 0..127
    const int acol4 = (tid & 1) * 4;     // 0 or 4
    // B-tile load mapping: 8 k-rows x 128 cols, one float4 per thread
    const int brow  = tid >> 5;          // 0..7
    const int bcol4 = (tid & 31) * 4;    // 0,4,...,124

    const bool a_valid = (arow < nrows);
    const float* a_ptr;
    if (LAYER == 1) {
        const int src = a_valid ? g_perm[row_start + arow] : 0;
        a_ptr = A + (size_t)src * E_DIM;
    } else {
        const int r = a_valid ? (row_start + arow) : 0;
        a_ptr = A + (size_t)r * H_DIM;
    }
    const float* w_ptr = W + (size_t)op * H_DIM + col_base;

    // 8x8 microtile per thread (16x16 thread grid)
    const int ty = tid >> 4;
    const int tx = tid & 15;

    float acc[8][8];
    #pragma unroll
    for (int i = 0; i < 8; i++)
        #pragma unroll
        for (int j = 0; j < 8; j++)
            acc[i][j] = 0.0f;

    const int K = 1024;
    for (int k0 = 0; k0 < K; k0 += BK) {
        float4 av = make_float4(0.f, 0.f, 0.f, 0.f);
        if (a_valid)
            av = *(const float4*)(a_ptr + k0 + acol4);
        As[acol4 + 0][arow] = av.x;
        As[acol4 + 1][arow] = av.y;
        As[acol4 + 2][arow] = av.z;
        As[acol4 + 3][arow] = av.w;

        const float4 bv =
            *(const float4*)(w_ptr + (size_t)(k0 + brow) * KOH + bcol4);
        *(float4*)&Bs[brow][bcol4] = bv;

        __syncthreads();

        #pragma unroll
        for (int kk = 0; kk < BK; kk++) {
            float a[8], b[8];
            *(float4*)&a[0] = *(const float4*)&As[kk][ty * 8];
            *(float4*)&a[4] = *(const float4*)&As[kk][ty * 8 + 4];
            *(float4*)&b[0] = *(const float4*)&Bs[kk][tx * 8];
            *(float4*)&b[4] = *(const float4*)&Bs[kk][tx * 8 + 4];
            #pragma unroll
            for (int i = 0; i < 8; i++)
                #pragma unroll
                for (int j = 0; j < 8; j++)
                    acc[i][j] += a[i] * b[j];
        }
        __syncthreads();
    }

    // Epilogue: bias + relu, masked rows, layer-dependent output placement
    const float* bptr = bias + op * H_DIM + col_base + tx * 8;
    float bv[8];
    *(float4*)&bv[0] = *(const float4*)&bptr[0];
    *(float4*)&bv[4] = *(const float4*)&bptr[4];

    #pragma unroll
    for (int i = 0; i < 8; i++) {
        const int r = ty * 8 + i;
        if (r >= nrows) break;
        float* optr;
        if (LAYER == 1) {
            optr = Out + (size_t)(row_start + r) * H_DIM + col_base + tx * 8;
        } else {
            const int dst = g_perm[row_start + r];
            optr = Out + (size_t)dst * H_DIM + col_base + tx * 8;
        }
        float4 v0, v1;
        v0.x = fmaxf(acc[i][0] + bv[0], 0.f);
        v0.y = fmaxf(acc[i][1] + bv[1], 0.f);
        v0.z = fmaxf(acc[i][2] + bv[2], 0.f);
        v0.w = fmaxf(acc[i][3] + bv[3], 0.f);
        v1.x = fmaxf(acc[i][4] + bv[4], 0.f);
        v1.y = fmaxf(acc[i][5] + bv[5], 0.f);
        v1.z = fmaxf(acc[i][6] + bv[6], 0.f);
        v1.w = fmaxf(acc[i][7] + bv[7], 0.f);
        *(float4*)&optr[0] = v0;
        *(float4*)&optr[4] = v1;
    }
}

// ============================================================================
// Launch
// ============================================================================
extern "C" void kernel_launch(void* const* d_in, const int* in_sizes, int n_in,
                              void* d_out, int out_size)
{
    const float* x      = (const float*)d_in[0];   // [B, E]
    const int*   op_idx = (const int*)  d_in[1];   // [B]
    const float* W1     = (const float*)d_in[2];   // [E, O, H]
    const float* b1     = (const float*)d_in[3];   // [O, H]
    const float* W2     = (const float*)d_in[4];   // [H, O, H]
    const float* b2     = (const float*)d_in[5];   // [O, H]
    float*       out    = (float*)d_out;           // [B, H]

    (void)in_sizes; (void)n_in; (void)out_size;

    float* h1;
    cudaGetSymbolAddress((void**)&h1, g_h1);

    setup_kernel<<<1, 512>>>(op_idx);

    dim3 grid(MAX_TILES, H_DIM / TN);
    gemm_kernel<1><<<grid, NTHREADS>>>(x,  W1, b1, h1);
    gemm_kernel<2><<<grid, NTHREADS>>>(h1, W2, b2, out);
}